// round 7
// baseline (speedup 1.0000x reference)
#include <cuda_runtime.h>
#include <math.h>

// Problem constants
#define BT   1024   // BS*T
#define NEN  64     // entities
#define ED   128    // entity dim
#define HYPD 256    // hypernet hidden
#define NA   16     // agents
#define NHD  4      // heads
#define HD   64     // head dim
#define EMB  32
#define NTHR 512

typedef unsigned long long u64;

// ---- packed fp32x2 helpers (Blackwell FFMA2; bitwise == 2x scalar fp32) ----
__device__ __forceinline__ void ffma2(u64 &d, u64 a, u64 b) {
    asm("fma.rn.f32x2 %0, %1, %2, %0;" : "+l"(d) : "l"(a), "l"(b));
}
__device__ __forceinline__ u64 splat2(float x) {
    u64 r; asm("mov.b64 %0, {%1, %1};" : "=l"(r) : "f"(x)); return r;
}
__device__ __forceinline__ u64 pack2(float x, float y) {
    u64 r; asm("mov.b64 %0, {%1, %2};" : "=l"(r) : "f"(x), "f"(y)); return r;
}
__device__ __forceinline__ float2 unpack2(u64 v) {
    float lo, hi; asm("mov.b64 {%0, %1}, %2;" : "=f"(lo), "=f"(hi) : "l"(v));
    return make_float2(lo, hi);
}

// -------- global scratch (static device arrays; no allocation) --------
__device__ float g_w1[BT * NA * EMB];
__device__ float g_b1[BT * EMB];
__device__ float g_wf[BT * EMB];
__device__ float g_vv[BT];

struct Ptrs { const float* p[31]; };

#define SMEM_FLOATS 57568

// ---------------------------------------------------------------------
// Tiled GEMM, K-paired f32x2 (zero packing MOVs).
// sOut[R][C] = epi( sA[R][K] @ gW[C][K]^T + bias ).  512 threads.
// wt: K-major tile wt[c][16] with per-c k-rotation swizzle.
// Thread -> cg = tid % NCG (NCG = C/4), rg = tid / NCG.
// Columns per thread: c = cg + j*NCG, j = 0..3 (strided).
// ---------------------------------------------------------------------
template<int R, int C, int K, bool BIAS, bool RELU, bool AMASK>
__device__ __forceinline__ void gemm(const float* __restrict__ sA,
                                     const float* __restrict__ gW,
                                     const float* __restrict__ gB,
                                     float* __restrict__ sOut,
                                     float* __restrict__ wt,
                                     const float* __restrict__ sAm,
                                     int tid)
{
    constexpr int KT  = 16;
    constexpr int TC  = 4;
    constexpr int NCG = C / TC;
    constexpr int NRG = NTHR / NCG;
    constexpr int RPG = (R + NRG - 1) / NRG;
    constexpr int NT  = K / KT;
    constexpr int K4  = KT / 4;                      // 4
    constexpr int TOT = C * K4;
    constexpr int LPT = (TOT + NTHR - 1) / NTHR;

    const int cg = tid % NCG;
    const int rg = tid / NCG;
    const int r0 = rg * RPG;
    const bool active = (r0 < R);
    const int swo = 4 * ((cg >> 1) & 3);             // k-rotation (same for all j)

    // staging coords
    int sc[LPT], sk4[LPT];
    bool sp[LPT];
#pragma unroll
    for (int l = 0; l < LPT; l++) {
        int idx = tid + l * NTHR;
        sp[l]  = (idx < TOT);
        sc[l]  = (idx < TOT) ? (idx / K4) : 0;
        sk4[l] = (idx < TOT) ? (idx % K4) : 0;
    }

    u64 acc[RPG][TC];
#pragma unroll
    for (int r = 0; r < RPG; r++)
#pragma unroll
        for (int j = 0; j < TC; j++) acc[r][j] = 0ULL;

    // prologue: fetch tile 0
    float4 st[LPT];
#pragma unroll
    for (int l = 0; l < LPT; l++)
        if (sp[l]) st[l] = *(const float4*)(gW + sc[l] * K + 4 * sk4[l]);

    for (int t = 0; t < NT; t++) {
        const int k0 = t * KT;
        __syncthreads();   // wt free
#pragma unroll
        for (int l = 0; l < LPT; l++) {
            if (sp[l]) {
                int c   = sc[l];
                int off = (4 * sk4[l] + 4 * ((c >> 1) & 3)) & 15;
                *(float4*)(wt + c * KT + off) = st[l];
            }
        }
        __syncthreads();   // wt visible
        if (t + 1 < NT) {
#pragma unroll
            for (int l = 0; l < LPT; l++)
                if (sp[l]) st[l] = *(const float4*)(gW + sc[l] * K + (k0 + KT) + 4 * sk4[l]);
        }
        if (active) {
#pragma unroll
            for (int kk = 0; kk < KT; kk += 4) {
                const int koff = (kk + swo) & 15;
                ulonglong2 w[TC];
#pragma unroll
                for (int j = 0; j < TC; j++)
                    w[j] = *(const ulonglong2*)(wt + (cg + j * NCG) * KT + koff);
#pragma unroll
                for (int r = 0; r < RPG; r++) {
                    ulonglong2 av = *(const ulonglong2*)(sA + (r0 + r) * K + k0 + kk);
#pragma unroll
                    for (int j = 0; j < TC; j++) {
                        ffma2(acc[r][j], av.x, w[j].x);
                        ffma2(acc[r][j], av.y, w[j].y);
                    }
                }
            }
        }
    }

    if (active) {
#pragma unroll
        for (int r = 0; r < RPG; r++) {
            int rr = r0 + r;
            float m = 1.f;
            if (AMASK) m = (sAm[rr] != 0.f) ? 0.f : 1.f;
#pragma unroll
            for (int j = 0; j < TC; j++) {
                int c = cg + j * NCG;
                float2 f = unpack2(acc[r][j]);
                float v = f.x + f.y;
                if (BIAS) v += gB[c];
                if (RELU) v = fmaxf(v, 0.f);
                sOut[rr * C + c] = v * m;
            }
        }
    }
}

// ---------------------------------------------------------------------
extern __shared__ float smem[];

__global__ void __launch_bounds__(NTHR)
hyper_kernel(Ptrs P)
{
    const int b   = blockIdx.x;
    const int h   = blockIdx.y;
    const int tid = threadIdx.x;

    const float* entities = P.p[1];
    const int*   emask    = (const int*)P.p[2];
    const int    base     = 3 + h * 7;
    const float* fc1_w = P.p[base + 0];
    const float* fc1_b = P.p[base + 1];
    const float* qkv_w = P.p[base + 2];
    const float* out_w = P.p[base + 3];
    const float* out_b = P.p[base + 4];
    const float* fc2_w = P.p[base + 5];
    const float* fc2_b = P.p[base + 6];

    float* sX1    = smem;             // 16384
    float* sK     = smem + 16384;     // 16384
    float* sV     = smem + 32768;     // 16384
    float* sQ     = smem + 49152;     // 4096 (E 8192 during fc1)
    float* sE     = smem + 49152;
    float* sAttn  = smem + 53248;     // 4096 (wtile V/Q here: 4096)
    float* sL     = sX1;              // 64x65 logits (X1 dead)
    float* sX3    = sX1 + 8192;       // 16x32
    float* sAttn2 = sK;               // 16x256 (K dead)
    float* sEm    = smem + 57408;     // 64
    float* sAm    = smem + 57472;     // 16
    float* sInv   = smem + 57488;     // 64

    __shared__ int sAnyZero;
    if (tid == 0) sAnyZero = 0;
    __syncthreads();

    if (tid < NEN) {
        int m = emask[b * NEN + tid];
        sEm[tid] = (float)m;
        if (tid < NA) sAm[tid] = (float)m;
        if (m == 0) atomicOr(&sAnyZero, 1);
    }
    {
        const float4* src = (const float4*)(entities + (size_t)b * NEN * ED);
        float4* dst = (float4*)sE;
        for (int i = tid; i < NEN * ED / 4; i += NTHR) dst[i] = src[i];
    }
    __syncthreads();

    // fc1: x1 = relu(E @ fc1_w^T + b)   A@sE, wtile@sK, out@sX1
    gemm<64, 256, 128, true, true, false>(sE, fc1_w, fc1_b, sX1, sK, nullptr, tid);
    __syncthreads();

    // K gemm: A@sX1, wtile@sV, out@sK
    gemm<64, 256, 256, false, false, false>(sX1, qkv_w + 256 * 256, nullptr, sK, sV, nullptr, tid);
    __syncthreads();
    // V gemm: A@sX1, wtile@sAttn, out@sV
    gemm<64, 256, 256, false, false, false>(sX1, qkv_w + 512 * 256, nullptr, sV, sAttn, nullptr, tid);
    __syncthreads();
    // Q gemm (16 rows): A@sX1, wtile@sAttn, out@sQ
    gemm<16, 256, 256, false, false, false>(sX1, qkv_w, nullptr, sQ, sAttn, nullptr, tid);
    __syncthreads();

    const int anyZero = sAnyZero;

    // ---------- attention ----------
    // Phase 1: logits. t -> (jg = t>>6, hq = t&63); each thread: 8 j's.
    {
        const int jg = tid >> 6;
        const int hq = tid & 63;
        const int hh = hq >> 4;
        const int i  = hq & 15;
        const float am_i = sAm[i];
        const float scale = 0.125f;  // 1/sqrt(64)

        u64 qp[32];
        const ulonglong2* qrow = (const ulonglong2*)(sQ + i * HYPD + hh * HD);
#pragma unroll
        for (int d4 = 0; d4 < 16; d4++) {
            ulonglong2 q = qrow[d4];
            qp[2 * d4 + 0] = q.x;
            qp[2 * d4 + 1] = q.y;
        }

#pragma unroll
        for (int jj = 0; jj < 8; jj++) {
            int j = jg * 8 + jj;
            const ulonglong2* krow = (const ulonglong2*)(sK + j * HYPD + hh * HD);
            u64 a0 = 0ULL, a1 = 0ULL;
#pragma unroll
            for (int d4 = 0; d4 < 16; d4++) {
                ulonglong2 kv = krow[d4];
                ffma2(a0, qp[2 * d4 + 0], kv.x);
                ffma2(a1, qp[2 * d4 + 1], kv.y);
            }
            float2 f0 = unpack2(a0);
            float2 f1 = unpack2(a1);
            float s = (f0.x + f0.y) + (f1.x + f1.y);
            const bool keep = (am_i == 0.f) && (sEm[j] == 0.f);
            sL[hq * 65 + j] = keep ? (s * scale) : -1e30f;
        }
    }
    __syncthreads();

    // Phase 2: softmax per row (64 threads)
    if (tid < 64) {
        const int hq = tid;
        const int i  = hq & 15;
        const float am_i = sAm[i];
        const bool allm = (am_i != 0.f) || (anyZero == 0);
        float* lrow = sL + hq * 65;
        float mx = -1e30f;
        for (int j = 0; j < NEN; j++) mx = fmaxf(mx, lrow[j]);
        float sum = 0.f;
        for (int j = 0; j < NEN; j++) {
            float e = expf(lrow[j] - mx);
            sum += e;
            lrow[j] = e;
        }
        sInv[hq] = allm ? 0.f : (1.f / sum);
    }
    __syncthreads();

    // Phase 3: AV. t -> (dg = t>>6, hq = t&63); each thread: 8 d's.
    {
        const int dg = tid >> 6;
        const int hq = tid & 63;
        const int hh = hq >> 4;
        const int i  = hq & 15;
        const int d0 = dg * 8;
        const float* lrow = sL + hq * 65;
        u64 acc[4] = {0ULL, 0ULL, 0ULL, 0ULL};
        for (int j = 0; j < NEN; j++) {
            u64 ps = splat2(lrow[j]);
            const ulonglong2* vrow = (const ulonglong2*)(sV + j * HYPD + hh * HD + d0);
            ulonglong2 va = vrow[0];
            ulonglong2 vb = vrow[1];
            ffma2(acc[0], ps, va.x);
            ffma2(acc[1], ps, va.y);
            ffma2(acc[2], ps, vb.x);
            ffma2(acc[3], ps, vb.y);
        }
        const float inv = sInv[hq];
        float* arow = sAttn + i * HYPD + hh * HD + d0;
#pragma unroll
        for (int q = 0; q < 4; q++) {
            float2 f = unpack2(acc[q]);
            arow[2 * q + 0] = f.x * inv;
            arow[2 * q + 1] = f.y * inv;
        }
    }
    __syncthreads();

    // out projection: A@sAttn, wtile@sX1 (logits dead), out@sAttn2(=sK)
    gemm<16, 256, 256, true, false, true>(sAttn, out_w, out_b, sAttn2, sX1, sAm, tid);
    __syncthreads();

    // fc2: A@sAttn2, wtile@sX1, out@sX3 (sX1+8192)
    gemm<16, 32, 256, true, false, true>(sAttn2, fc2_w, fc2_b, sX3, sX1, sAm, tid);
    __syncthreads();

    // mode-specific reductions -> global scratch
    if (h == 0) {
        for (int idx = tid; idx < NA * EMB; idx += NTHR)
            g_w1[(size_t)b * NA * EMB + idx] = fabsf(sX3[idx]);
    } else if (h == 1) {
        if (tid < EMB) {
            float s = 0.f;
            for (int i = 0; i < NA; i++) s += sX3[i * EMB + tid];
            g_b1[b * EMB + tid] = s * (1.f / 16.f);
        }
    } else if (h == 2) {
        if (tid < EMB) {
            float s = 0.f;
            for (int i = 0; i < NA; i++) s += sX3[i * EMB + tid];
            g_wf[b * EMB + tid] = fabsf(s * (1.f / 16.f));
        }
    } else {
        if (tid < EMB) {
            float s = 0.f;
            for (int i = 0; i < NA; i++) s += sX3[i * EMB + tid];
            sInv[tid] = s;
        }
        __syncthreads();
        if (tid == 0) {
            float t = 0.f;
            for (int e = 0; e < EMB; e++) t += sInv[e];
            g_vv[b] = t * (1.f / 512.f);
        }
    }
}

// ---------------------------------------------------------------------
__global__ void __launch_bounds__(256)
mix_kernel(const float* __restrict__ qs, float* __restrict__ out)
{
    const int warp = threadIdx.x >> 5;
    const int lane = threadIdx.x & 31;
    const int b = blockIdx.x * 8 + warp;
    const int e = lane;

    float s = g_b1[b * EMB + e];
#pragma unroll
    for (int a = 0; a < NA; a++)
        s += qs[b * NA + a] * g_w1[(b * NA + a) * EMB + e];
    float hdn = (s > 0.f) ? s : expm1f(s);
    float t = hdn * g_wf[b * EMB + e];
#pragma unroll
    for (int off = 16; off > 0; off >>= 1)
        t += __shfl_xor_sync(0xFFFFFFFF, t, off);
    if (lane == 0) out[b] = t + g_vv[b];
}

// Tiny no-op kernel: shifts ncu's skip window so -s 5 -c 1 lands on hyper_kernel.
__global__ void dummy_kernel() {}

// ---------------------------------------------------------------------
extern "C" void kernel_launch(void* const* d_in, const int* in_sizes, int n_in,
                              void* d_out, int out_size)
{
    Ptrs P;
    for (int i = 0; i < 31; i++) P.p[i] = (const float*)d_in[i];

    const size_t smem_bytes = (size_t)SMEM_FLOATS * sizeof(float);
    cudaFuncSetAttribute(hyper_kernel,
                         cudaFuncAttributeMaxDynamicSharedMemorySize,
                         (int)smem_bytes);

    dummy_kernel<<<1, 32>>>();
    hyper_kernel<<<dim3(BT, 4), NTHR, smem_bytes>>>(P);
    dummy_kernel<<<1, 32>>>();
    mix_kernel<<<BT / 8, 256>>>((const float*)d_in[0], (float*)d_out);
}